// round 1
// baseline (speedup 1.0000x reference)
#include <cuda_runtime.h>
#include <math_constants.h>

#define SDIM 2048
#define BDIM 32
#define HDIM 1024

// Scratch (no device allocs allowed)
__device__ float g_u[BDIM * HDIM];       // u[b,h] = sum_k hidden[b,k] * W[k,h]
__device__ float g_scores[BDIM * SDIM];  // scores[b,s]

// ---------------------------------------------------------------------------
// Kernel 1: u = hidden @ W   (32 x 1024 x 1024, tiny)
// block: (32,32) -> x = h within 32-wide tile, y = b. grid: 32 blocks over h.
// W[k*H + h] coalesced across x; hidden[b*H+k] broadcast within a warp;
// all warps in a block touch the same W line -> L1 broadcast.
// ---------------------------------------------------------------------------
__global__ void proj_kernel(const float* __restrict__ hidden,
                            const float* __restrict__ W) {
    const int h = blockIdx.x * 32 + threadIdx.x;
    const int b = threadIdx.y;
    const float* __restrict__ hrow = hidden + b * HDIM;
    float acc = 0.0f;
#pragma unroll 8
    for (int k = 0; k < HDIM; ++k) {
        acc = fmaf(hrow[k], W[k * HDIM + h], acc);
    }
    g_u[b * HDIM + h] = acc;
}

// ---------------------------------------------------------------------------
// Kernel 2: scores[b,s] = u[b] . enc[s,b,:]
// One warp per (s,b) row (4KB contiguous). r = s*B + b maps consecutive
// warps to consecutive memory rows -> perfect streaming of 268 MB.
// ---------------------------------------------------------------------------
__global__ void score_kernel(const float* __restrict__ enc) {
    const int warp = (blockIdx.x * blockDim.x + threadIdx.x) >> 5;
    const int lane = threadIdx.x & 31;
    if (warp >= SDIM * BDIM) return;

    const int b = warp & (BDIM - 1);
    const int s = warp >> 5;  // warp / BDIM

    const float4* __restrict__ erow =
        reinterpret_cast<const float4*>(enc + (size_t)warp * HDIM);
    const float4* __restrict__ urow =
        reinterpret_cast<const float4*>(g_u + b * HDIM);

    float acc = 0.0f;
#pragma unroll
    for (int j = 0; j < 8; ++j) {
        float4 e = erow[j * 32 + lane];
        float4 u = urow[j * 32 + lane];
        acc = fmaf(e.x, u.x, acc);
        acc = fmaf(e.y, u.y, acc);
        acc = fmaf(e.z, u.z, acc);
        acc = fmaf(e.w, u.w, acc);
    }
#pragma unroll
    for (int off = 16; off > 0; off >>= 1)
        acc += __shfl_xor_sync(0xFFFFFFFFu, acc, off);

    if (lane == 0) g_scores[b * SDIM + s] = acc;
}

// ---------------------------------------------------------------------------
// Kernel 3: softmax over s per b. One block (256 threads) per b; each thread
// owns 8 values in registers. Note: the hidden.bias constant term per b is
// invariant under softmax and was dropped upstream.
// ---------------------------------------------------------------------------
__global__ void softmax_kernel(float* __restrict__ out) {
    const int b = blockIdx.x;
    const int tid = threadIdx.x;
    const float* __restrict__ row = g_scores + b * SDIM;

    __shared__ float sred[32];

    float vals[8];
    float vmax = -CUDART_INF_F;
#pragma unroll
    for (int j = 0; j < 8; ++j) {
        float v = row[tid + j * 256];
        vals[j] = v;
        vmax = fmaxf(vmax, v);
    }
    // block max
#pragma unroll
    for (int off = 16; off > 0; off >>= 1)
        vmax = fmaxf(vmax, __shfl_xor_sync(0xFFFFFFFFu, vmax, off));
    if ((tid & 31) == 0) sred[tid >> 5] = vmax;
    __syncthreads();
    if (tid < 32) {
        float v = sred[tid & 7];  // 8 warps
#pragma unroll
        for (int off = 4; off > 0; off >>= 1)
            v = fmaxf(v, __shfl_xor_sync(0xFFFFFFFFu, v, off));
        sred[0] = v;
    }
    __syncthreads();
    vmax = sred[0];
    __syncthreads();

    float lsum = 0.0f;
#pragma unroll
    for (int j = 0; j < 8; ++j) {
        vals[j] = __expf(vals[j] - vmax);
        lsum += vals[j];
    }
    // block sum
#pragma unroll
    for (int off = 16; off > 0; off >>= 1)
        lsum += __shfl_xor_sync(0xFFFFFFFFu, lsum, off);
    if ((tid & 31) == 0) sred[tid >> 5] = lsum;
    __syncthreads();
    if (tid < 32) {
        float v = sred[tid & 7];
#pragma unroll
        for (int off = 4; off > 0; off >>= 1)
            v += __shfl_xor_sync(0xFFFFFFFFu, v, off);
        sred[0] = v;
    }
    __syncthreads();
    const float inv = 1.0f / sred[0];

#pragma unroll
    for (int j = 0; j < 8; ++j)
        out[b * SDIM + tid + j * 256] = vals[j] * inv;
}

// ---------------------------------------------------------------------------
extern "C" void kernel_launch(void* const* d_in, const int* in_sizes, int n_in,
                              void* d_out, int out_size) {
    const float* hidden = (const float*)d_in[0];  // [B,H]
    const float* enc    = (const float*)d_in[1];  // [S,B,H]
    const float* W      = (const float*)d_in[2];  // [H,H]
    // d_in[3] = bias [H] -- provably invariant under softmax, unused.
    float* out = (float*)d_out;                   // [1,B,S]

    dim3 pb(32, 32);
    proj_kernel<<<HDIM / 32, pb>>>(hidden, W);

    const int total_warps = SDIM * BDIM;          // 65536
    const int threads = 256;                      // 8 warps/block
    const int blocks = (total_warps * 32) / threads;
    score_kernel<<<blocks, threads>>>(enc);

    softmax_kernel<<<BDIM, 256>>>(out);
}

// round 2
// speedup vs baseline: 2.3437x; 2.3437x over previous
#include <cuda_runtime.h>
#include <math_constants.h>

#define SDIM 2048
#define BDIM 32
#define HDIM 1024

#define KS 16          // k-splits
#define KT (HDIM / KS) // 64 k per split
#define HT 128         // h per block tile (8 tiles)

// Scratch (no device allocs allowed)
__device__ float g_part[KS * BDIM * HDIM];  // split-K partials (2 MB)
__device__ float g_u[BDIM * HDIM];          // u[b,h] = hidden @ W
__device__ float g_scores[BDIM * SDIM];     // scores[b,s]

// ---------------------------------------------------------------------------
// Kernel 1a: split-K tiled GEMM  u_part[ks] = hidden[:, krange] @ W[krange, htile]
// grid = (8 h-tiles, 16 k-splits) = 128 blocks, 256 threads each.
// ---------------------------------------------------------------------------
__global__ __launch_bounds__(256) void proj_kernel(
    const float* __restrict__ hidden, const float* __restrict__ W) {
    __shared__ float4 sW[KT * (HT / 4)];   // [64 k][32 float4-h] = 32 KB
    __shared__ float  sH[BDIM * KT];       // [32 b][64 k] = 8 KB

    const int h0 = blockIdx.x * HT;
    const int k0 = blockIdx.y * KT;
    const int tid = threadIdx.x;

    // Load W tile: 64 rows x 128 cols as float4, coalesced.
    const float4* __restrict__ Wg = reinterpret_cast<const float4*>(W);
#pragma unroll
    for (int i = 0; i < (KT * HT / 4) / 256; ++i) {   // 8 iters
        int idx = tid + i * 256;                       // 0..2047
        int kk = idx >> 5;                             // /32
        int c  = idx & 31;
        sW[idx] = Wg[(size_t)(k0 + kk) * (HDIM / 4) + (h0 >> 2) + c];
    }
    // Load hidden tile: 32 b x 64 k, coalesced in k.
#pragma unroll
    for (int i = 0; i < (BDIM * KT) / 256; ++i) {     // 8 iters
        int idx = tid + i * 256;
        int bb = idx >> 6;                             // /64
        int kk = idx & 63;
        sH[idx] = hidden[bb * HDIM + k0 + kk];
    }
    __syncthreads();

    const int lane = tid & 31;         // h4 index (covers 128 h)
    const int b0 = (tid >> 5) * 4;     // 8 warps x 4 b = 32 b

    float4 acc0 = {0,0,0,0}, acc1 = {0,0,0,0}, acc2 = {0,0,0,0}, acc3 = {0,0,0,0};
#pragma unroll 8
    for (int k = 0; k < KT; ++k) {
        float4 w4 = sW[k * 32 + lane];
        float h0v = sH[(b0 + 0) * KT + k];
        float h1v = sH[(b0 + 1) * KT + k];
        float h2v = sH[(b0 + 2) * KT + k];
        float h3v = sH[(b0 + 3) * KT + k];
        acc0.x = fmaf(h0v, w4.x, acc0.x); acc0.y = fmaf(h0v, w4.y, acc0.y);
        acc0.z = fmaf(h0v, w4.z, acc0.z); acc0.w = fmaf(h0v, w4.w, acc0.w);
        acc1.x = fmaf(h1v, w4.x, acc1.x); acc1.y = fmaf(h1v, w4.y, acc1.y);
        acc1.z = fmaf(h1v, w4.z, acc1.z); acc1.w = fmaf(h1v, w4.w, acc1.w);
        acc2.x = fmaf(h2v, w4.x, acc2.x); acc2.y = fmaf(h2v, w4.y, acc2.y);
        acc2.z = fmaf(h2v, w4.z, acc2.z); acc2.w = fmaf(h2v, w4.w, acc2.w);
        acc3.x = fmaf(h3v, w4.x, acc3.x); acc3.y = fmaf(h3v, w4.y, acc3.y);
        acc3.z = fmaf(h3v, w4.z, acc3.z); acc3.w = fmaf(h3v, w4.w, acc3.w);
    }

    float4* __restrict__ part4 = reinterpret_cast<float4*>(
        g_part + (size_t)blockIdx.y * BDIM * HDIM);
    const int hbase4 = (h0 >> 2) + lane;
    part4[(b0 + 0) * (HDIM / 4) + hbase4] = acc0;
    part4[(b0 + 1) * (HDIM / 4) + hbase4] = acc1;
    part4[(b0 + 2) * (HDIM / 4) + hbase4] = acc2;
    part4[(b0 + 3) * (HDIM / 4) + hbase4] = acc3;
}

// ---------------------------------------------------------------------------
// Kernel 1b: fold split-K partials (deterministic, fixed order).
// ---------------------------------------------------------------------------
__global__ __launch_bounds__(256) void reduce_kernel() {
    const int idx = blockIdx.x * 256 + threadIdx.x;   // 0..32767
    float s = 0.0f;
#pragma unroll
    for (int j = 0; j < KS; ++j) s += g_part[j * (BDIM * HDIM) + idx];
    g_u[idx] = s;
}

// ---------------------------------------------------------------------------
// Kernel 2: scores[b,s] = u[b] . enc[s,b,:]   (HBM-roofline streaming, 268 MB)
// One warp per (s,b) row.
// ---------------------------------------------------------------------------
__global__ void score_kernel(const float* __restrict__ enc) {
    const int warp = (blockIdx.x * blockDim.x + threadIdx.x) >> 5;
    const int lane = threadIdx.x & 31;
    if (warp >= SDIM * BDIM) return;

    const int b = warp & (BDIM - 1);
    const int s = warp >> 5;

    const float4* __restrict__ erow =
        reinterpret_cast<const float4*>(enc + (size_t)warp * HDIM);
    const float4* __restrict__ urow =
        reinterpret_cast<const float4*>(g_u + b * HDIM);

    float acc = 0.0f;
#pragma unroll
    for (int j = 0; j < 8; ++j) {
        float4 e = erow[j * 32 + lane];
        float4 u = urow[j * 32 + lane];
        acc = fmaf(e.x, u.x, acc);
        acc = fmaf(e.y, u.y, acc);
        acc = fmaf(e.z, u.z, acc);
        acc = fmaf(e.w, u.w, acc);
    }
#pragma unroll
    for (int off = 16; off > 0; off >>= 1)
        acc += __shfl_xor_sync(0xFFFFFFFFu, acc, off);

    if (lane == 0) g_scores[b * SDIM + s] = acc;
}

// ---------------------------------------------------------------------------
// Kernel 3: softmax over s per b. One block per b.
// (hidden.bias constant per b is invariant under softmax -> dropped.)
// ---------------------------------------------------------------------------
__global__ void softmax_kernel(float* __restrict__ out) {
    const int b = blockIdx.x;
    const int tid = threadIdx.x;
    const float* __restrict__ row = g_scores + b * SDIM;

    __shared__ float sred[32];

    float vals[8];
    float vmax = -CUDART_INF_F;
#pragma unroll
    for (int j = 0; j < 8; ++j) {
        float v = row[tid + j * 256];
        vals[j] = v;
        vmax = fmaxf(vmax, v);
    }
#pragma unroll
    for (int off = 16; off > 0; off >>= 1)
        vmax = fmaxf(vmax, __shfl_xor_sync(0xFFFFFFFFu, vmax, off));
    if ((tid & 31) == 0) sred[tid >> 5] = vmax;
    __syncthreads();
    if (tid < 32) {
        float v = sred[tid & 7];
#pragma unroll
        for (int off = 4; off > 0; off >>= 1)
            v = fmaxf(v, __shfl_xor_sync(0xFFFFFFFFu, v, off));
        sred[0] = v;
    }
    __syncthreads();
    vmax = sred[0];
    __syncthreads();

    float lsum = 0.0f;
#pragma unroll
    for (int j = 0; j < 8; ++j) {
        vals[j] = __expf(vals[j] - vmax);
        lsum += vals[j];
    }
#pragma unroll
    for (int off = 16; off > 0; off >>= 1)
        lsum += __shfl_xor_sync(0xFFFFFFFFu, lsum, off);
    if ((tid & 31) == 0) sred[tid >> 5] = lsum;
    __syncthreads();
    if (tid < 32) {
        float v = sred[tid & 7];
#pragma unroll
        for (int off = 4; off > 0; off >>= 1)
            v += __shfl_xor_sync(0xFFFFFFFFu, v, off);
        sred[0] = v;
    }
    __syncthreads();
    const float inv = 1.0f / sred[0];

#pragma unroll
    for (int j = 0; j < 8; ++j)
        out[b * SDIM + tid + j * 256] = vals[j] * inv;
}

// ---------------------------------------------------------------------------
extern "C" void kernel_launch(void* const* d_in, const int* in_sizes, int n_in,
                              void* d_out, int out_size) {
    const float* hidden = (const float*)d_in[0];  // [B,H]
    const float* enc    = (const float*)d_in[1];  // [S,B,H]
    const float* W      = (const float*)d_in[2];  // [H,H]
    float* out = (float*)d_out;                   // [1,B,S]

    dim3 pg(HDIM / HT, KS);                       // (8, 16)
    proj_kernel<<<pg, 256>>>(hidden, W);
    reduce_kernel<<<(BDIM * HDIM) / 256, 256>>>();

    const int total_warps = SDIM * BDIM;          // 65536
    score_kernel<<<total_warps * 32 / 256, 256>>>(enc);

    softmax_kernel<<<BDIM, 256>>>(out);
}

// round 3
// speedup vs baseline: 2.4522x; 1.0463x over previous
#include <cuda_runtime.h>
#include <math_constants.h>

#define SDIM 2048
#define BDIM 32
#define HDIM 1024

#define KS 16          // k-splits
#define KT (HDIM / KS) // 64 k per split
#define HT 128         // h per block tile (8 tiles)

// Scratch (no device allocs allowed)
__device__ float g_part[KS * BDIM * HDIM];  // split-K partials (2 MB)
__device__ float g_u[BDIM * HDIM];          // u[b,h] = hidden @ W
__device__ float g_scores[BDIM * SDIM];     // scores[b,s]

// ---------------------------------------------------------------------------
// Kernel 1a: split-K tiled GEMM  u_part = hidden[:, krange] @ W[krange, htile]
// grid = (8 h-tiles, 16 k-splits) = 128 blocks, 256 threads.
// ---------------------------------------------------------------------------
__global__ __launch_bounds__(256) void proj_kernel(
    const float* __restrict__ hidden, const float* __restrict__ W) {
    __shared__ float4 sW[KT * (HT / 4)];   // 32 KB
    __shared__ float  sH[BDIM * KT];       // 8 KB

    const int h0 = blockIdx.x * HT;
    const int k0 = blockIdx.y * KT;
    const int tid = threadIdx.x;

    const float4* __restrict__ Wg = reinterpret_cast<const float4*>(W);
#pragma unroll
    for (int i = 0; i < (KT * HT / 4) / 256; ++i) {   // 8 iters
        int idx = tid + i * 256;
        int kk = idx >> 5;
        int c  = idx & 31;
        sW[idx] = Wg[(size_t)(k0 + kk) * (HDIM / 4) + (h0 >> 2) + c];
    }
#pragma unroll
    for (int i = 0; i < (BDIM * KT) / 256; ++i) {     // 8 iters
        int idx = tid + i * 256;
        int bb = idx >> 6;
        int kk = idx & 63;
        sH[idx] = hidden[bb * HDIM + k0 + kk];
    }
    __syncthreads();

    const int lane = tid & 31;
    const int b0 = (tid >> 5) * 4;

    float4 acc0 = {0,0,0,0}, acc1 = {0,0,0,0}, acc2 = {0,0,0,0}, acc3 = {0,0,0,0};
#pragma unroll 8
    for (int k = 0; k < KT; ++k) {
        float4 w4 = sW[k * 32 + lane];
        float h0v = sH[(b0 + 0) * KT + k];
        float h1v = sH[(b0 + 1) * KT + k];
        float h2v = sH[(b0 + 2) * KT + k];
        float h3v = sH[(b0 + 3) * KT + k];
        acc0.x = fmaf(h0v, w4.x, acc0.x); acc0.y = fmaf(h0v, w4.y, acc0.y);
        acc0.z = fmaf(h0v, w4.z, acc0.z); acc0.w = fmaf(h0v, w4.w, acc0.w);
        acc1.x = fmaf(h1v, w4.x, acc1.x); acc1.y = fmaf(h1v, w4.y, acc1.y);
        acc1.z = fmaf(h1v, w4.z, acc1.z); acc1.w = fmaf(h1v, w4.w, acc1.w);
        acc2.x = fmaf(h2v, w4.x, acc2.x); acc2.y = fmaf(h2v, w4.y, acc2.y);
        acc2.z = fmaf(h2v, w4.z, acc2.z); acc2.w = fmaf(h2v, w4.w, acc2.w);
        acc3.x = fmaf(h3v, w4.x, acc3.x); acc3.y = fmaf(h3v, w4.y, acc3.y);
        acc3.z = fmaf(h3v, w4.z, acc3.z); acc3.w = fmaf(h3v, w4.w, acc3.w);
    }

    float4* __restrict__ part4 = reinterpret_cast<float4*>(
        g_part + (size_t)blockIdx.y * BDIM * HDIM);
    const int hbase4 = (h0 >> 2) + lane;
    part4[(b0 + 0) * (HDIM / 4) + hbase4] = acc0;
    part4[(b0 + 1) * (HDIM / 4) + hbase4] = acc1;
    part4[(b0 + 2) * (HDIM / 4) + hbase4] = acc2;
    part4[(b0 + 3) * (HDIM / 4) + hbase4] = acc3;
}

// ---------------------------------------------------------------------------
// Kernel 1b: fold split-K partials (deterministic fixed order).
// ---------------------------------------------------------------------------
__global__ __launch_bounds__(256) void reduce_kernel() {
    const int idx = blockIdx.x * 256 + threadIdx.x;
    float s = 0.0f;
#pragma unroll
    for (int j = 0; j < KS; ++j) s += g_part[j * (BDIM * HDIM) + idx];
    g_u[idx] = s;
}

// ---------------------------------------------------------------------------
// Kernel 2: scores[b,s] = u[b] . enc[s,b,:]  — HBM-roofline stream of 268 MB.
// enc: evict-first streaming loads (__ldcs); u: cached (L2-resident, 128 KB).
// ---------------------------------------------------------------------------
__global__ __launch_bounds__(256) void score_kernel(const float* __restrict__ enc) {
    const int warp = (blockIdx.x * blockDim.x + threadIdx.x) >> 5;
    const int lane = threadIdx.x & 31;
    if (warp >= SDIM * BDIM) return;

    const int b = warp & (BDIM - 1);
    const int s = warp >> 5;

    const float4* __restrict__ erow =
        reinterpret_cast<const float4*>(enc + (size_t)warp * HDIM);
    const float4* __restrict__ urow =
        reinterpret_cast<const float4*>(g_u + b * HDIM);

    float acc = 0.0f;
#pragma unroll
    for (int j = 0; j < 8; ++j) {
        float4 e = __ldcs(&erow[j * 32 + lane]);   // streaming, evict-first
        float4 u = __ldg(&urow[j * 32 + lane]);    // cached
        acc = fmaf(e.x, u.x, acc);
        acc = fmaf(e.y, u.y, acc);
        acc = fmaf(e.z, u.z, acc);
        acc = fmaf(e.w, u.w, acc);
    }
#pragma unroll
    for (int off = 16; off > 0; off >>= 1)
        acc += __shfl_xor_sync(0xFFFFFFFFu, acc, off);

    if (lane == 0) g_scores[b * SDIM + s] = acc;
}

// ---------------------------------------------------------------------------
// Kernel 3: softmax over s per b. 32 blocks x 1024 threads, 2 vals/thread —
// short serial chain, 3-level reduction.
// ---------------------------------------------------------------------------
__global__ __launch_bounds__(1024) void softmax_kernel(float* __restrict__ out) {
    const int b = blockIdx.x;
    const int tid = threadIdx.x;
    const float* __restrict__ row = g_scores + b * SDIM;

    __shared__ float sred[32];

    float v0 = row[tid];
    float v1 = row[tid + 1024];
    float vmax = fmaxf(v0, v1);
#pragma unroll
    for (int off = 16; off > 0; off >>= 1)
        vmax = fmaxf(vmax, __shfl_xor_sync(0xFFFFFFFFu, vmax, off));
    if ((tid & 31) == 0) sred[tid >> 5] = vmax;
    __syncthreads();
    if (tid < 32) {
        float v = sred[tid];
#pragma unroll
        for (int off = 16; off > 0; off >>= 1)
            v = fmaxf(v, __shfl_xor_sync(0xFFFFFFFFu, v, off));
        sred[0] = v;
    }
    __syncthreads();
    vmax = sred[0];
    __syncthreads();

    v0 = __expf(v0 - vmax);
    v1 = __expf(v1 - vmax);
    float lsum = v0 + v1;
#pragma unroll
    for (int off = 16; off > 0; off >>= 1)
        lsum += __shfl_xor_sync(0xFFFFFFFFu, lsum, off);
    if ((tid & 31) == 0) sred[tid >> 5] = lsum;
    __syncthreads();
    if (tid < 32) {
        float v = sred[tid];
#pragma unroll
        for (int off = 16; off > 0; off >>= 1)
            v += __shfl_xor_sync(0xFFFFFFFFu, v, off);
        sred[0] = v;
    }
    __syncthreads();
    const float inv = 1.0f / sred[0];

    out[b * SDIM + tid]        = v0 * inv;
    out[b * SDIM + tid + 1024] = v1 * inv;
}

// ---------------------------------------------------------------------------
extern "C" void kernel_launch(void* const* d_in, const int* in_sizes, int n_in,
                              void* d_out, int out_size) {
    const float* hidden = (const float*)d_in[0];  // [B,H]
    const float* enc    = (const float*)d_in[1];  // [S,B,H]
    const float* W      = (const float*)d_in[2];  // [H,H]
    float* out = (float*)d_out;                   // [1,B,S]

    dim3 pg(HDIM / HT, KS);                       // (8, 16)
    proj_kernel<<<pg, 256>>>(hidden, W);
    reduce_kernel<<<(BDIM * HDIM) / 256, 256>>>();

    const int total_warps = SDIM * BDIM;          // 65536
    score_kernel<<<total_warps * 32 / 256, 256>>>(enc);

    softmax_kernel<<<BDIM, 1024>>>(out);
}